// round 17
// baseline (speedup 1.0000x reference)
#include <cuda_runtime.h>

#define H 15
#define NPACK 541
// packed-weight layout (u64 {w,w} per weight), t-space scaling folded in:
// W1,b1 scaled by -log2(e); W2,W3,W4 unscaled; b2,b3,b4 scaled by -log2(e).
#define OW1 0      // 30
#define OB1 30     // 15
#define OW2 45     // 225
#define OB2 270    // 15
#define OW3 285    // 225
#define OB3 510    // 15
#define OW4 525    // 15
#define OB4 540    // 1

typedef unsigned long long u64;

__device__ u64 g_packed[NPACK];
__constant__ u64 cw[NPACK];

// ---- packed f32x2 helpers (sm_100+ PTX) ----
__device__ __forceinline__ u64 pk(float a, float b) {
    u64 r; asm("mov.b64 %0,{%1,%2};" : "=l"(r) : "f"(a), "f"(b)); return r;
}
__device__ __forceinline__ u64 fma2(u64 a, u64 b, u64 c) {
    u64 r; asm("fma.rn.f32x2 %0,%1,%2,%3;" : "=l"(r) : "l"(a), "l"(b), "l"(c)); return r;
}

// Fused SiLU (t-space): t = -log2e*a from the pre-scaled GEMV.
// g = t * rcp(1 + ex2(t)) = -log2e * SiLU(a); compensation folds into the
// next (linear) layer's weights. Single asm region: all temps internal so
// ptxas can pin the f32 halves onto the b64 pair (no cross-boundary MOVs).
__device__ __forceinline__ u64 act2(u64 t) {
    u64 h;
    asm("{\n\t"
        ".reg .f32 t0,t1,e0,e1,r0,r1,g0,g1;\n\t"
        "mov.b64 {t0,t1},%1;\n\t"
        "ex2.approx.f32 e0,t0;\n\t"
        "ex2.approx.f32 e1,t1;\n\t"
        "add.f32 e0,e0,0f3F800000;\n\t"
        "add.f32 e1,e1,0f3F800000;\n\t"
        "rcp.approx.f32 r0,e0;\n\t"
        "rcp.approx.f32 r1,e1;\n\t"
        "mul.f32 g0,t0,r0;\n\t"
        "mul.f32 g1,t1,r1;\n\t"
        "mov.b64 %0,{g0,g1};\n\t"
        "}" : "=l"(h) : "l"(t));
    return h;
}

// Final sigmoid, fused, packed result: sigma(a) = rcp(1 + ex2(t))
__device__ __forceinline__ u64 sig2(u64 t) {
    u64 s;
    asm("{\n\t"
        ".reg .f32 t0,t1,e0,e1,r0,r1;\n\t"
        "mov.b64 {t0,t1},%1;\n\t"
        "ex2.approx.f32 e0,t0;\n\t"
        "ex2.approx.f32 e1,t1;\n\t"
        "add.f32 e0,e0,0f3F800000;\n\t"
        "add.f32 e1,e1,0f3F800000;\n\t"
        "rcp.approx.f32 r0,e0;\n\t"
        "rcp.approx.f32 r1,e1;\n\t"
        "mov.b64 %0,{r0,r1};\n\t"
        "}" : "=l"(s) : "l"(t));
    return s;
}

#define NLOG2E (-1.4426950408889634f)

// Duplicate each scalar weight into a {w',w'} u64 pair with t-space scaling.
__global__ void prep_kernel(const float* __restrict__ W1, const float* __restrict__ b1,
                            const float* __restrict__ W2, const float* __restrict__ b2,
                            const float* __restrict__ W3, const float* __restrict__ b3,
                            const float* __restrict__ W4, const float* __restrict__ b4) {
    int i = threadIdx.x;
    float v;
    if      (i < OB1) v = W1[i - OW1] * NLOG2E;   // W1 scaled
    else if (i < OW2) v = b1[i - OB1] * NLOG2E;   // b1 scaled
    else if (i < OB2) v = W2[i - OW2];            // W2 unscaled
    else if (i < OW3) v = b2[i - OB2] * NLOG2E;   // b2 scaled
    else if (i < OB3) v = W3[i - OW3];            // W3 unscaled
    else if (i < OW4) v = b3[i - OB3] * NLOG2E;   // b3 scaled
    else if (i < OB4) v = W4[i - OW4];            // W4 unscaled
    else if (i == OB4) v = b4[0] * NLOG2E;        // b4 scaled
    else return;
    u64 p; asm("mov.b64 %0,{%1,%1};" : "=l"(p) : "f"(v));
    g_packed[i] = p;
}

// 2 rows per thread, packed f32x2 math, weights as uniform LDCU from constant
// memory (immediate indexing -> LDCU floor 1, separate uniform port).
__global__ __launch_bounds__(128) void mlp2_kernel(const float4* __restrict__ x,
                                                   u64* __restrict__ out,
                                                   int npair) {
    int i = blockIdx.x * blockDim.x + threadIdx.x;

    float4 xv = x[i];                  // {x0,y0,x1,y1} = rows 2i, 2i+1
    u64 xx = pk(xv.x, xv.z);
    u64 yy = pk(xv.y, xv.w);

    u64 h1[H], h2[H];

    // Layer 1: Linear(2,H)*-log2e -> act
#pragma unroll
    for (int k = 0; k < H; k++) {
        u64 t = fma2(xx, cw[OW1 + k], fma2(yy, cw[OW1 + H + k], cw[OB1 + k]));
        h1[k] = act2(t);
    }

    // Layer 2: Linear(H,H) -> act
#pragma unroll
    for (int k = 0; k < H; k++) {
        u64 t = cw[OB2 + k];
#pragma unroll
        for (int j = 0; j < H; j++) t = fma2(h1[j], cw[OW2 + j * H + k], t);
        h2[k] = act2(t);
    }

    // Layer 3 (reuse h1)
#pragma unroll
    for (int k = 0; k < H; k++) {
        u64 t = cw[OB3 + k];
#pragma unroll
        for (int j = 0; j < H; j++) t = fma2(h2[j], cw[OW3 + j * H + k], t);
        h1[k] = act2(t);
    }

    // Layer 4 + sigmoid (packed store: two fp32 outputs as one u64)
    u64 t = cw[OB4];
#pragma unroll
    for (int j = 0; j < H; j++) t = fma2(h1[j], cw[OW4 + j], t);

    out[i] = sig2(t);
}

extern "C" void kernel_launch(void* const* d_in, const int* in_sizes, int n_in,
                              void* d_out, int out_size) {
    // Inputs: x, W1, b1, W2, b2, W3, b3, W4, b4
    const float* x = (const float*)d_in[0];

    prep_kernel<<<1, 544>>>((const float*)d_in[1], (const float*)d_in[2],
                            (const float*)d_in[3], (const float*)d_in[4],
                            (const float*)d_in[5], (const float*)d_in[6],
                            (const float*)d_in[7], (const float*)d_in[8]);

    void* src = nullptr;
    cudaGetSymbolAddress(&src, g_packed);  // host-side query, capture-safe
    cudaMemcpyToSymbolAsync(cw, src, NPACK * sizeof(u64), 0,
                            cudaMemcpyDeviceToDevice, 0);

    int n = in_sizes[0] / 2;   // rows
    int npair = n / 2;         // 2 rows per thread (exact: n = 2^21)
    int threads = 128;
    int blocks = npair / threads;
    mlp2_kernel<<<blocks, threads>>>((const float4*)x, (u64*)d_out, npair);
}